// round 6
// baseline (speedup 1.0000x reference)
#include <cuda_runtime.h>
#include <cub/cub.cuh>
#include <stdint.h>

// ---------------------------------------------------------------------------
// Sparse average pooling — replicating the reference's ACTUAL semantics.
//
// The reference's `.astype(jnp.int64)` runs under JAX default x64-disabled,
// so keys are int32 and ((b*2048+q0)*2048+q1)*2048+q2 overflows:
//   b*2^33 mod 2^32 == 0  ->  batch drops out of the key.
//   residue q0*2^22 + q1*2^11 + q2 < 2^31 (q<=499)  ->  exact, positive.
// Effective grouping/order: ascending lexicographic (q0,q1,q2), batch ignored.
//
// key = (q0<<18)|(q1<<9)|q2  (order-isomorphic, 27 bits)
// rank = position in ascending sorted distinct-key list (CUB sort + scan).
// ---------------------------------------------------------------------------

#define MAXN (1 << 20)
#define TEMP_BYTES ((size_t)(64u << 20))

__device__ uint32_t g_keys[MAXN];
__device__ uint32_t g_keys_s[MAXN];
__device__ uint32_t g_vals[MAXN];
__device__ uint32_t g_vals_s[MAXN];
__device__ uint32_t g_flags[MAXN];
__device__ uint32_t g_segid[MAXN];
__device__ uint32_t g_rankf[MAXN];   // rank | 0x80000000 if NOT first point of voxel
__device__ uint32_t g_count[MAXN];
__device__ uint32_t g_nflist[MAXN];
__device__ uint32_t g_nfcount;
__device__ unsigned char g_temp[TEMP_BYTES];

// ---- clear ---------------------------------------------------------------

__global__ void k_clear_counts(int n) {
    int i = blockIdx.x * blockDim.x + threadIdx.x;
    if (i < n) g_count[i] = 0;
    if (i == 0) g_nfcount = 0;
}

// ---- pass 1: packed keys (batch EXCLUDED) + iota values -------------------

__global__ void k_keys(const int4* __restrict__ coords, int n) {
    int i = blockIdx.x * blockDim.x + threadIdx.x;
    if (i >= n) return;
    int4 c = coords[i];
    uint32_t key = ((uint32_t)(c.x >> 1) << 18) |
                   ((uint32_t)(c.y >> 1) << 9)  |
                    (uint32_t)(c.z >> 1);
    g_keys[i] = key;
    g_vals[i] = (uint32_t)i;
}

// ---- pass 2 (after sort): head flags --------------------------------------

__global__ void k_headflag(int n) {
    int j = blockIdx.x * blockDim.x + threadIdx.x;
    if (j >= n) return;
    g_flags[j] = (j == 0) || (g_keys_s[j] != g_keys_s[j - 1]);
}

// ---- pass 3 (after scan): scatter ranks, counts, first-point coords -------

__global__ void k_scatter(const int4* __restrict__ coords,
                          float4* __restrict__ outC, int n) {
    int j = blockIdx.x * blockDim.x + threadIdx.x;
    if (j >= n) return;
    uint32_t r = g_segid[j] - 1u;          // rank in sorted-unique order
    uint32_t i = g_vals_s[j];              // original point index
    atomicAdd(&g_count[r], 1u);
    if (g_flags[j]) {                      // sorted-first point of this voxel
        g_rankf[i] = r;
        int4 c = coords[i];
        outC[r] = make_float4((float)c.x, (float)c.y, (float)c.z, (float)c.w);
    } else {
        g_rankf[i] = r | 0x80000000u;
        uint32_t pos = atomicAdd(&g_nfcount, 1u);
        g_nflist[pos] = i;
    }
}

// ---- pass 4: first-point feat copy (16 threads / point, float4) -----------

__global__ void k_featstore(const float4* __restrict__ feats4,
                            float4* __restrict__ outF4, int n) {
    int i = blockIdx.x * 16 + (threadIdx.x >> 4);
    int l = threadIdx.x & 15;
    if (i >= n) return;
    uint32_t r = g_rankf[i];
    float4 v = feats4[(size_t)i * 16 + l];
    if (!(r & 0x80000000u))
        outF4[(size_t)r * 16 + l] = v;
}

// ---- pass 5: residual (non-first) atomic adds (~8k points) ----------------

__global__ void k_residual(const int4* __restrict__ coords,
                           const float* __restrict__ feats,
                           float* __restrict__ outC, float* __restrict__ outF) {
    uint32_t cnt = g_nfcount;
    for (uint32_t idx = blockIdx.x * blockDim.x + threadIdx.x; idx < cnt;
         idx += gridDim.x * blockDim.x) {
        uint32_t i = g_nflist[idx];
        uint32_t r = g_rankf[i] & 0x7fffffffu;
        int4 c = coords[i];
        atomicAdd(&outC[(size_t)r * 4 + 0], (float)c.x);
        atomicAdd(&outC[(size_t)r * 4 + 1], (float)c.y);
        atomicAdd(&outC[(size_t)r * 4 + 2], (float)c.z);
        atomicAdd(&outC[(size_t)r * 4 + 3], (float)c.w);
        const float* f = feats + (size_t)i * 64;
        float* o = outF + (size_t)r * 64;
        #pragma unroll
        for (int d = 0; d < 64; d++) atomicAdd(&o[d], f[d]);
    }
}

// ---- pass 6: finalize — zero empty slots, divide multi-point slots --------

__global__ void k_finalize(float* __restrict__ outC, float* __restrict__ outF,
                           int n) {
    int u = blockIdx.x * blockDim.x + threadIdx.x;
    if (u >= n) return;
    uint32_t c = g_count[u];
    if (c == 1u) return;                    // singleton: already exact
    float4* oc = reinterpret_cast<float4*>(outC) + u;
    float4* of = reinterpret_cast<float4*>(outF) + (size_t)u * 16;
    if (c == 0u) {                          // empty padded slot -> zeros
        float4 z = make_float4(0.f, 0.f, 0.f, 0.f);
        *oc = z;
        #pragma unroll
        for (int j = 0; j < 16; j++) of[j] = z;
    } else {                                // divide; round-half-even coords
        float fc = (float)c;
        float4 v = *oc;
        v.x = rintf(v.x / fc); v.y = rintf(v.y / fc);
        v.z = rintf(v.z / fc); v.w = rintf(v.w / fc);
        *oc = v;
        #pragma unroll
        for (int j = 0; j < 16; j++) {
            float4 f = of[j];
            f.x /= fc; f.y /= fc; f.z /= fc; f.w /= fc;
            of[j] = f;
        }
    }
}

// ---------------------------------------------------------------------------

extern "C" void kernel_launch(void* const* d_in, const int* in_sizes, int n_in,
                              void* d_out, int out_size) {
    const int4*  coords = (const int4*)d_in[0];   // [N,4] int32
    const float* feats  = (const float*)d_in[1];  // [N,64] float32
    const int n = in_sizes[0] / 4;

    float* outC = (float*)d_out;                  // [N,4]
    float* outF = outC + (size_t)n * 4;           // [N,64]

    const int TPB = 256;
    const int nb = (n + TPB - 1) / TPB;

    // Device addresses of static scratch (no allocation anywhere).
    void* p_temp   = nullptr;
    void* p_keys   = nullptr; void* p_keys_s = nullptr;
    void* p_vals   = nullptr; void* p_vals_s = nullptr;
    void* p_flags  = nullptr; void* p_segid  = nullptr;
    cudaGetSymbolAddress(&p_temp,   g_temp);
    cudaGetSymbolAddress(&p_keys,   g_keys);
    cudaGetSymbolAddress(&p_keys_s, g_keys_s);
    cudaGetSymbolAddress(&p_vals,   g_vals);
    cudaGetSymbolAddress(&p_vals_s, g_vals_s);
    cudaGetSymbolAddress(&p_flags,  g_flags);
    cudaGetSymbolAddress(&p_segid,  g_segid);

    k_clear_counts<<<nb, TPB>>>(n);
    k_keys<<<nb, TPB>>>(coords, n);

    // Sort (key, index) pairs on the 27-bit batch-free key.
    size_t tb = TEMP_BYTES;
    cub::DeviceRadixSort::SortPairs(
        p_temp, tb,
        (const uint32_t*)p_keys, (uint32_t*)p_keys_s,
        (const uint32_t*)p_vals, (uint32_t*)p_vals_s,
        n, 0, 27);

    k_headflag<<<nb, TPB>>>(n);

    // Inclusive sum of head flags -> 1-based segment ids.
    size_t tb2 = TEMP_BYTES;
    cub::DeviceScan::InclusiveSum(
        p_temp, tb2,
        (const uint32_t*)p_flags, (uint32_t*)p_segid, n);

    k_scatter<<<nb, TPB>>>(coords, (float4*)outC, n);
    k_featstore<<<(n + 15) / 16, 256>>>((const float4*)feats, (float4*)outF, n);
    k_residual<<<64, 256>>>(coords, feats, outC, outF);
    k_finalize<<<nb, TPB>>>(outC, outF, n);
}

// round 8
// speedup vs baseline: 1.1978x; 1.1978x over previous
#include <cuda_runtime.h>
#include <stdint.h>

// ---------------------------------------------------------------------------
// Sparse average pooling — reference's effective semantics (int32 overflow
// drops the batch term): group/order by ascending lexicographic (q0,q1,q2).
//
// key = (q0<<18)|(q1<<9)|q2   (27 bits, q = coord>>1, coord in [0,1000))
// rank(key) = #distinct keys < key, via 2^27-bit occupancy bitmap (16 MB,
// L2-resident) + hierarchical popcount prefix. Scan machinery identical to
// the R2 implementation, which R5's CUB cross-check proved correct.
// ---------------------------------------------------------------------------

#define NWORDS  (1u << 22)           // 2^27 bits / 32
#define NCHUNKS 4096                 // NWORDS / 1024 words per chunk
#define MAXN    (1 << 20)

__device__ uint32_t g_bitmap[NWORDS];
__device__ uint2    g_wp[NWORDS];    // {exclusive word prefix, bitmap word}
__device__ uint32_t g_chunksum[NCHUNKS];
__device__ uint32_t g_chunkprefix[NCHUNKS];
__device__ uint32_t g_rankf[MAXN];   // rank | 0x80000000 if NOT first point
__device__ uint32_t g_count[MAXN];
__device__ uint32_t g_nflist[MAXN];
__device__ uint32_t g_nfcount;

__device__ __forceinline__ uint32_t warp_incl_scan(uint32_t v) {
    #pragma unroll
    for (int d = 1; d < 32; d <<= 1) {
        uint32_t nv = __shfl_up_sync(0xffffffffu, v, d);
        if ((threadIdx.x & 31) >= (unsigned)d) v += nv;
    }
    return v;
}

__device__ __forceinline__ uint32_t pack_key(int4 c) {
    return ((uint32_t)(c.x >> 1) << 18) | ((uint32_t)(c.y >> 1) << 9) |
            (uint32_t)(c.z >> 1);
}

// ---- pass 0: clear bitmap + counts (one kernel) ---------------------------

__global__ void k_clear(int n) {
    uint32_t i = blockIdx.x * blockDim.x + threadIdx.x;   // 1M threads
    reinterpret_cast<uint4*>(g_bitmap)[i] = make_uint4(0, 0, 0, 0);
    if ((int)i < n) g_count[i] = 0;
    if (i == 0) g_nfcount = 0;
}

// ---- pass 1: set occupancy bits -------------------------------------------

__global__ void k_keys(const int4* __restrict__ coords, int n) {
    int i = blockIdx.x * blockDim.x + threadIdx.x;
    if (i >= n) return;
    uint32_t key = pack_key(coords[i]);
    atomicOr(&g_bitmap[key >> 5], 1u << (key & 31u));
}

// ---- pass 2: per-chunk popcount sums (chunk = 1024 words) -----------------

__global__ void k_chunksum() {
    const uint4* bm4 = reinterpret_cast<const uint4*>(g_bitmap);
    uint4 v = bm4[blockIdx.x * 256 + threadIdx.x];
    uint32_t s = __popc(v.x) + __popc(v.y) + __popc(v.z) + __popc(v.w);
    s += __shfl_down_sync(0xffffffffu, s, 16);
    s += __shfl_down_sync(0xffffffffu, s, 8);
    s += __shfl_down_sync(0xffffffffu, s, 4);
    s += __shfl_down_sync(0xffffffffu, s, 2);
    s += __shfl_down_sync(0xffffffffu, s, 1);
    __shared__ uint32_t wsum[8];
    int wid = threadIdx.x >> 5;
    if ((threadIdx.x & 31) == 0) wsum[wid] = s;
    __syncthreads();
    if (threadIdx.x == 0) {
        uint32_t t = 0;
        #pragma unroll
        for (int j = 0; j < 8; j++) t += wsum[j];
        g_chunksum[blockIdx.x] = t;
    }
}

// ---- pass 3: exclusive scan of 4096 chunk sums (1 block, 1024 thr) --------

__global__ void k_chunkscan() {
    int t = threadIdx.x;
    uint32_t local[4];
    uint32_t s = 0;
    #pragma unroll
    for (int j = 0; j < 4; j++) {
        local[j] = s;
        s += g_chunksum[t * 4 + j];
    }
    uint32_t incl = warp_incl_scan(s);
    __shared__ uint32_t wsum[32];
    int wid = t >> 5;
    if ((t & 31) == 31) wsum[wid] = incl;
    __syncthreads();
    if (wid == 0) {
        uint32_t w = wsum[t & 31];
        w = warp_incl_scan(w);
        wsum[t & 31] = w;
    }
    __syncthreads();
    uint32_t excl = incl - s + (wid ? wsum[wid - 1] : 0u);
    #pragma unroll
    for (int j = 0; j < 4; j++)
        g_chunkprefix[t * 4 + j] = excl + local[j];
}

// ---- pass 4: fused {word prefix, word} table -------------------------------

__global__ void k_wordprefix() {
    const uint4* bm4 = reinterpret_cast<const uint4*>(g_bitmap);
    int t = threadIdx.x;
    uint32_t base_idx = blockIdx.x * 256 + t;
    uint4 v = bm4[base_idx];
    uint32_t p0 = __popc(v.x), p1 = __popc(v.y), p2 = __popc(v.z), p3 = __popc(v.w);
    uint32_t s = p0 + p1 + p2 + p3;
    uint32_t incl = warp_incl_scan(s);
    __shared__ uint32_t wsum[8];
    int wid = t >> 5;
    if ((t & 31) == 31) wsum[wid] = incl;
    __syncthreads();
    uint32_t wexcl = 0;
    for (int j = 0; j < wid; j++) wexcl += wsum[j];
    uint32_t base = g_chunkprefix[blockIdx.x] + wexcl + (incl - s);
    uint2* wp = g_wp + base_idx * 4;
    wp[0] = make_uint2(base, v.x);
    wp[1] = make_uint2(base + p0, v.y);
    wp[2] = make_uint2(base + p0 + p1, v.z);
    wp[3] = make_uint2(base + p0 + p1 + p2, v.w);
}

// ---- pass 5: rank, counts, first-point coord stores -----------------------

__global__ void k_rank(const int4* __restrict__ coords,
                       float4* __restrict__ outC, int n) {
    int i = blockIdx.x * blockDim.x + threadIdx.x;
    if (i >= n) return;
    int4 c = coords[i];
    uint32_t key = pack_key(c);
    uint2 wp = g_wp[key >> 5];
    uint32_t rank = wp.x + __popc(wp.y & ((1u << (key & 31u)) - 1u));
    uint32_t old = atomicAdd(&g_count[rank], 1u);
    if (old == 0) {
        g_rankf[i] = rank;
        outC[rank] = make_float4((float)c.x, (float)c.y, (float)c.z, (float)c.w);
    } else {
        g_rankf[i] = rank | 0x80000000u;
        uint32_t pos = atomicAdd(&g_nfcount, 1u);
        g_nflist[pos] = i;
    }
}

// ---- pass 6: first-point feat copy (16 threads / point, float4) -----------

__global__ void k_featstore(const float4* __restrict__ feats4,
                            float4* __restrict__ outF4, int n) {
    int i = blockIdx.x * 16 + (threadIdx.x >> 4);
    int l = threadIdx.x & 15;
    if (i >= n) return;
    uint32_t r = g_rankf[i];
    float4 v = feats4[(size_t)i * 16 + l];
    if (!(r & 0x80000000u))
        outF4[(size_t)r * 16 + l] = v;
}

// ---- pass 7: residual (non-first) atomic adds (~8k points) ----------------

__global__ void k_residual(const int4* __restrict__ coords,
                           const float* __restrict__ feats,
                           float* __restrict__ outC, float* __restrict__ outF) {
    uint32_t cnt = g_nfcount;
    for (uint32_t idx = blockIdx.x * blockDim.x + threadIdx.x; idx < cnt;
         idx += gridDim.x * blockDim.x) {
        uint32_t i = g_nflist[idx];
        uint32_t r = g_rankf[i] & 0x7fffffffu;
        int4 c = coords[i];
        atomicAdd(&outC[(size_t)r * 4 + 0], (float)c.x);
        atomicAdd(&outC[(size_t)r * 4 + 1], (float)c.y);
        atomicAdd(&outC[(size_t)r * 4 + 2], (float)c.z);
        atomicAdd(&outC[(size_t)r * 4 + 3], (float)c.w);
        const float* f = feats + (size_t)i * 64;
        float* o = outF + (size_t)r * 64;
        #pragma unroll
        for (int d = 0; d < 64; d++) atomicAdd(&o[d], f[d]);
    }
}

// ---- pass 8: finalize — zero empty slots, divide multi-point slots --------

__global__ void k_finalize(float* __restrict__ outC, float* __restrict__ outF,
                           int n) {
    int u = blockIdx.x * blockDim.x + threadIdx.x;
    if (u >= n) return;
    uint32_t c = g_count[u];
    if (c == 1u) return;                    // singleton: already exact
    float4* oc = reinterpret_cast<float4*>(outC) + u;
    float4* of = reinterpret_cast<float4*>(outF) + (size_t)u * 16;
    if (c == 0u) {                          // empty padded slot -> zeros
        float4 z = make_float4(0.f, 0.f, 0.f, 0.f);
        *oc = z;
        #pragma unroll
        for (int j = 0; j < 16; j++) of[j] = z;
    } else {                                // divide; round-half-even coords
        float fc = (float)c;
        float4 v = *oc;
        v.x = rintf(v.x / fc); v.y = rintf(v.y / fc);
        v.z = rintf(v.z / fc); v.w = rintf(v.w / fc);
        *oc = v;
        #pragma unroll
        for (int j = 0; j < 16; j++) {
            float4 f = of[j];
            f.x /= fc; f.y /= fc; f.z /= fc; f.w /= fc;
            of[j] = f;
        }
    }
}

// ---------------------------------------------------------------------------

extern "C" void kernel_launch(void* const* d_in, const int* in_sizes, int n_in,
                              void* d_out, int out_size) {
    const int4*  coords = (const int4*)d_in[0];   // [N,4] int32
    const float* feats  = (const float*)d_in[1];  // [N,64] float32
    const int n = in_sizes[0] / 4;

    float* outC = (float*)d_out;                  // [N,4]
    float* outF = outC + (size_t)n * 4;           // [N,64]

    const int TPB = 256;
    const int nb = (n + TPB - 1) / TPB;

    k_clear<<<NWORDS / 4 / TPB, TPB>>>(n);        // 1M threads
    k_keys<<<nb, TPB>>>(coords, n);
    k_chunksum<<<NCHUNKS, 256>>>();
    k_chunkscan<<<1, 1024>>>();
    k_wordprefix<<<NCHUNKS, 256>>>();
    k_rank<<<nb, TPB>>>(coords, (float4*)outC, n);
    k_featstore<<<(n + 15) / 16, 256>>>((const float4*)feats, (float4*)outF, n);
    k_residual<<<64, 256>>>(coords, feats, outC, outF);
    k_finalize<<<nb, TPB>>>(outC, outF, n);
}